// round 14
// baseline (speedup 1.0000x reference)
#include <cuda_runtime.h>

#define N_FEAT 1024
#define N_LAYER 4
#define THREADS 256        // one float4 per thread covers a 1024-float row
#define R 4                // rows per block

// Precomputed: hc[0]=h01, hc[1]=h02+h12, hc[2]=h03+h13+h23 where h_ji=<b_j,w_i>
__device__ float g_hc[3];
__device__ float g_bsum[N_FEAT];
__device__ float g_hraw[N_LAYER][N_LAYER];

__global__ __launch_bounds__(1024) void precompute_kernel(
    const float* __restrict__ w, const float* __restrict__ b)
{
    int tid = threadIdx.x;  // 1024 threads
    float s = 0.f;
    #pragma unroll
    for (int j = 0; j < N_LAYER; j++) s += b[j * N_FEAT + tid];
    g_bsum[tid] = s;

    int wid = tid >> 5, lane = tid & 31;
    if (wid < N_LAYER * N_LAYER) {
        int j = wid >> 2, i = wid & 3;
        float acc = 0.f;
        #pragma unroll
        for (int k = lane; k < N_FEAT; k += 32)
            acc += b[j * N_FEAT + k] * w[i * N_FEAT + k];
        #pragma unroll
        for (int o = 16; o; o >>= 1)
            acc += __shfl_xor_sync(0xffffffffu, acc, o);
        if (lane == 0) g_hraw[j][i] = acc;
    }
    __syncthreads();
    if (tid == 0) {
        g_hc[0] = g_hraw[0][1];
        g_hc[1] = g_hraw[0][2] + g_hraw[1][2];
        g_hc[2] = g_hraw[0][3] + g_hraw[1][3] + g_hraw[2][3];
    }
}

__device__ __forceinline__ float dot4(float4 a, float4 b) {
    return a.x * b.x + a.y * b.y + a.z * b.z + a.w * b.w;
}

__global__ __launch_bounds__(THREADS, 6) void cross_kernel(
    const float* __restrict__ x, const float* __restrict__ w,
    float* __restrict__ out)
{
    __shared__ float4 part[R][THREADS];  // per-thread dot partials (16 KB)
    __shared__ float  s4s[R];

    const int t    = threadIdx.x;
    const int lane = t & 31;
    const int warp = t >> 5;

    const size_t base = (size_t)blockIdx.x * R * (N_FEAT / 4);
    const float4* xp = (const float4*)x + base;
    float4*       op = (float4*)out + base;

    // ── Phase A: dot partials, no shuffles — one STS.128 per row
    {
        const float4* w4 = (const float4*)w;
        const float4 w0 = __ldg(w4 + 0 * (N_FEAT / 4) + t);
        const float4 w1 = __ldg(w4 + 1 * (N_FEAT / 4) + t);
        const float4 w2 = __ldg(w4 + 2 * (N_FEAT / 4) + t);
        const float4 w3 = __ldg(w4 + 3 * (N_FEAT / 4) + t);
        #pragma unroll
        for (int r = 0; r < R; r++) {
            const float4 xv = __ldg(xp + (size_t)r * (N_FEAT / 4) + t);
            float4 p;
            p.x = dot4(xv, w0);
            p.y = dot4(xv, w1);
            p.z = dot4(xv, w2);
            p.w = dot4(xv, w3);
            part[r][t] = p;
        }
    }
    __syncthreads();

    // ── Phase B: warp r reduces row r (8 LDS.128 + 20 SHFL)
    if (warp < R) {
        float4 acc = part[warp][lane];
        #pragma unroll
        for (int j = 1; j < 8; j++) {
            float4 v = part[warp][lane + 32 * j];
            acc.x += v.x; acc.y += v.y; acc.z += v.z; acc.w += v.w;
        }
        #pragma unroll
        for (int o = 16; o; o >>= 1) {
            acc.x += __shfl_xor_sync(0xffffffffu, acc.x, o);
            acc.y += __shfl_xor_sync(0xffffffffu, acc.y, o);
            acc.z += __shfl_xor_sync(0xffffffffu, acc.z, o);
            acc.w += __shfl_xor_sync(0xffffffffu, acc.w, o);
        }
        if (lane == 0) {
            const float s1 = 1.f + acc.x;
            const float s2 = s1 + s1 * acc.y + g_hc[0];
            const float s3 = s2 + s2 * acc.z + g_hc[1];
            const float s4 = s3 + s3 * acc.w + g_hc[2];
            s4s[warp] = s4;
        }
    }
    __syncthreads();

    // ── Phase C: re-read x (L1-hot), scale, add bsum, store
    {
        const float4 bs = __ldg((const float4*)g_bsum + t);
        float sc[R];
        #pragma unroll
        for (int r = 0; r < R; r++) sc[r] = s4s[r];

        #pragma unroll
        for (int r = 0; r < R; r++) {
            const float4 xv = __ldg(xp + (size_t)r * (N_FEAT / 4) + t);
            float4 o;
            o.x = sc[r] * xv.x + bs.x;
            o.y = sc[r] * xv.y + bs.y;
            o.z = sc[r] * xv.z + bs.z;
            o.w = sc[r] * xv.w + bs.w;
            op[(size_t)r * (N_FEAT / 4) + t] = o;
        }
    }
}

extern "C" void kernel_launch(void* const* d_in, const int* in_sizes, int n_in,
                              void* d_out, int out_size) {
    const float* x = (const float*)d_in[0];
    const float* w = (const float*)d_in[1];
    const float* b = (const float*)d_in[2];
    float* out = (float*)d_out;
    int n_rows = in_sizes[0] / N_FEAT;  // 16384

    precompute_kernel<<<1, 1024>>>(w, b);
    cross_kernel<<<n_rows / R, THREADS>>>(x, w, out);
}

// round 15
// speedup vs baseline: 1.0208x; 1.0208x over previous
#include <cuda_runtime.h>

#define N_FEAT 1024
#define N_LAYER 4
#define THREADS 256        // one float4 per thread covers a 1024-float row
#define R 4                // rows per block

// Precomputed: hc[0]=h01, hc[1]=h02+h12, hc[2]=h03+h13+h23 where h_ji=<b_j,w_i>
__device__ float g_hc[3];
__device__ float g_bsum[N_FEAT];
__device__ float g_hraw[N_LAYER][N_LAYER];

__global__ __launch_bounds__(1024) void precompute_kernel(
    const float* __restrict__ w, const float* __restrict__ b)
{
    int tid = threadIdx.x;  // 1024 threads
    float s = 0.f;
    #pragma unroll
    for (int j = 0; j < N_LAYER; j++) s += b[j * N_FEAT + tid];
    g_bsum[tid] = s;

    int wid = tid >> 5, lane = tid & 31;
    if (wid < N_LAYER * N_LAYER) {
        int j = wid >> 2, i = wid & 3;
        float acc = 0.f;
        #pragma unroll
        for (int k = lane; k < N_FEAT; k += 32)
            acc += b[j * N_FEAT + k] * w[i * N_FEAT + k];
        #pragma unroll
        for (int o = 16; o; o >>= 1)
            acc += __shfl_xor_sync(0xffffffffu, acc, o);
        if (lane == 0) g_hraw[j][i] = acc;
    }
    __syncthreads();
    if (tid == 0) {
        g_hc[0] = g_hraw[0][1];
        g_hc[1] = g_hraw[0][2] + g_hraw[1][2];
        g_hc[2] = g_hraw[0][3] + g_hraw[1][3] + g_hraw[2][3];
    }
}

__device__ __forceinline__ float dot4(float4 a, float4 b) {
    return a.x * b.x + a.y * b.y + a.z * b.z + a.w * b.w;
}

__global__ __launch_bounds__(THREADS, 6) void cross_kernel(
    const float* __restrict__ x, const float* __restrict__ w,
    float* __restrict__ out)
{
    __shared__ float4 part[R][THREADS];  // per-thread dot partials (16 KB)
    __shared__ float  s4s[R];

    const int t    = threadIdx.x;
    const int lane = t & 31;
    const int warp = t >> 5;

    const size_t base = (size_t)blockIdx.x * R * (N_FEAT / 4);
    const float4* xp = (const float4*)x + base;
    float4*       op = (float4*)out + base;

    // ── Phase A: dot partials, no shuffles — one STS.128 per row
    {
        const float4* w4 = (const float4*)w;
        const float4 w0 = __ldg(w4 + 0 * (N_FEAT / 4) + t);
        const float4 w1 = __ldg(w4 + 1 * (N_FEAT / 4) + t);
        const float4 w2 = __ldg(w4 + 2 * (N_FEAT / 4) + t);
        const float4 w3 = __ldg(w4 + 3 * (N_FEAT / 4) + t);
        #pragma unroll
        for (int r = 0; r < R; r++) {
            const float4 xv = __ldg(xp + (size_t)r * (N_FEAT / 4) + t);
            float4 p;
            p.x = dot4(xv, w0);
            p.y = dot4(xv, w1);
            p.z = dot4(xv, w2);
            p.w = dot4(xv, w3);
            part[r][t] = p;
        }
    }
    __syncthreads();

    // ── Phase B: warp r reduces row r (8 LDS.128 + 20 SHFL)
    if (warp < R) {
        float4 acc = part[warp][lane];
        #pragma unroll
        for (int j = 1; j < 8; j++) {
            float4 v = part[warp][lane + 32 * j];
            acc.x += v.x; acc.y += v.y; acc.z += v.z; acc.w += v.w;
        }
        #pragma unroll
        for (int o = 16; o; o >>= 1) {
            acc.x += __shfl_xor_sync(0xffffffffu, acc.x, o);
            acc.y += __shfl_xor_sync(0xffffffffu, acc.y, o);
            acc.z += __shfl_xor_sync(0xffffffffu, acc.z, o);
            acc.w += __shfl_xor_sync(0xffffffffu, acc.w, o);
        }
        if (lane == 0) {
            const float s1 = 1.f + acc.x;
            const float s2 = s1 + s1 * acc.y + g_hc[0];
            const float s3 = s2 + s2 * acc.z + g_hc[1];
            const float s4 = s3 + s3 * acc.w + g_hc[2];
            s4s[warp] = s4;
        }
    }
    __syncthreads();

    // ── Phase C: re-read x (L1-hot), scale, add bsum, store
    {
        const float4 bs = __ldg((const float4*)g_bsum + t);
        float sc[R];
        #pragma unroll
        for (int r = 0; r < R; r++) sc[r] = s4s[r];

        #pragma unroll
        for (int r = 0; r < R; r++) {
            const float4 xv = __ldg(xp + (size_t)r * (N_FEAT / 4) + t);
            float4 o;
            o.x = sc[r] * xv.x + bs.x;
            o.y = sc[r] * xv.y + bs.y;
            o.z = sc[r] * xv.z + bs.z;
            o.w = sc[r] * xv.w + bs.w;
            op[(size_t)r * (N_FEAT / 4) + t] = o;
        }
    }
}

extern "C" void kernel_launch(void* const* d_in, const int* in_sizes, int n_in,
                              void* d_out, int out_size) {
    const float* x = (const float*)d_in[0];
    const float* w = (const float*)d_in[1];
    const float* b = (const float*)d_in[2];
    float* out = (float*)d_out;
    int n_rows = in_sizes[0] / N_FEAT;  // 16384

    precompute_kernel<<<1, 1024>>>(w, b);
    cross_kernel<<<n_rows / R, THREADS>>>(x, w, out);
}